// round 14
// baseline (speedup 1.0000x reference)
#include <cuda_runtime.h>
#include <cstddef>

#define B_DIM 256
#define D_DIM 4096
#define D4    (4 * D_DIM)

// ---------------- scratch (static __device__ globals; no allocation) --------
__device__ float g_recurrent[B_DIM * D_DIM];   // 4 MB
__device__ float g_asm_act [B_DIM * D_DIM];    // 4 MB
__device__ float g_asm_rec [B_DIM * D_DIM];    // 4 MB
__device__ float g_mod     [B_DIM * D_DIM];    // 4 MB
__device__ float g_hidden  [B_DIM * D_DIM];    // 4 MB
__device__ float g_statsW  [2 * D_DIM];        // rowmax, rowsumexp
__device__ float g_statsRW [2 * D_DIM];

// ---------------- epilogue argument bundle ----------------------------------
struct EpiArgs {
    const float* e0;
    const float* e1;
    const float* e2;
    const float* e3;
    const float* e4;
    float*       out;
};

// EPI codes:
// 0 STORE      : out[r*N+c] = acc                          (out = g_recurrent)
// 1 ACTS       : relu(relu(acc + rec) - 0.5*(1 - gaba + glut)) -> d_out acts
// 2 HEBB       : (W + w_sm*M) - decay[r]*W                 -> d_out W_new/RW_new
// 3 BIASRELU   : relu(acc + b1[c])                         (out = g_hidden)
// 4 NEURO      : t = tanh(acc + b2[c]); scatter dop/ser/glu/gab into d_out
//
// AMODE: 0 = A row-major [M,K];  1 = A row-major [K,M] (used for a_sm^T @ mod)
//
// NUMERICS: per output element the dot product is a sequential ascending-k
// FMA chain, restarted every `kc` elements; slab partials are folded into a
// running total left-to-right with plain fp32 adds (deterministic split-K=2
// ordering for kc = K/2, matching the reference backend's cublas config).
// Elementwise ops mirror the jax expression tree with non-contractible
// __f*_rn intrinsics.

template<int AMODE, int EPI>
__global__ void __launch_bounds__(256, 2)
sgemm_kernel(const float* __restrict__ A, const float* __restrict__ Bm,
             int M, int N, int K, int kc, EpiArgs ea)
{
    constexpr int BM = 64, BN = 128, BK = 16, TM = 4, TN = 8;
    __shared__ float As[BK][BM];
    __shared__ float Bs[BK][BN];

    const int tid = threadIdx.x;          // 256 threads
    const int tx  = tid & 15;             // 0..15  -> 8 consecutive cols
    const int ty  = tid >> 4;             // 0..15  -> 4 consecutive rows
    const int n0  = blockIdx.x * BN;
    const int m0  = blockIdx.y * BM;

    // A-load mapping
    const int a_r  = tid >> 2;            // AMODE 0: row in tile (0..63)
    const int a_c  = (tid & 3) * 4;       // AMODE 0: k offset {0,4,8,12}
    const int at_r = tid >> 4;            // AMODE 1: k row (0..15)
    const int at_c = (tid & 15) * 4;      // AMODE 1: m offset
    // B-load mapping: 16x128 tile, 2 float4 per thread
    const int b_r = tid >> 5;             // 0..7
    const int b_c = (tid & 31) * 4;

    float tot[TM][TN];   // running sum of completed slabs
    float acc[TM][TN];   // current slab's sequential FMA chain
#pragma unroll
    for (int i = 0; i < TM; i++)
#pragma unroll
        for (int j = 0; j < TN; j++) { tot[i][j] = 0.f; acc[i][j] = 0.f; }

    for (int k0 = 0; k0 < K; k0 += BK) {
        float4 av;
        if (AMODE == 0)
            av = *(const float4*)(A + (size_t)(m0 + a_r) * K + k0 + a_c);
        else
            av = *(const float4*)(A + (size_t)(k0 + at_r) * M + m0 + at_c);
        float4 bv0 = *(const float4*)(Bm + (size_t)(k0 + b_r)     * N + n0 + b_c);
        float4 bv1 = *(const float4*)(Bm + (size_t)(k0 + b_r + 8) * N + n0 + b_c);

        __syncthreads();
        if (AMODE == 0) {
            As[a_c + 0][a_r] = av.x;
            As[a_c + 1][a_r] = av.y;
            As[a_c + 2][a_r] = av.z;
            As[a_c + 3][a_r] = av.w;
        } else {
            *(float4*)&As[at_r][at_c] = av;
        }
        *(float4*)&Bs[b_r][b_c]     = bv0;
        *(float4*)&Bs[b_r + 8][b_c] = bv1;
        __syncthreads();

#pragma unroll
        for (int k = 0; k < BK; k++) {
            float a[TM], b[TN];
            *(float4*)a       = *(float4*)&As[k][ty * TM];
            *(float4*)&b[0]   = *(float4*)&Bs[k][tx * TN];
            *(float4*)&b[4]   = *(float4*)&Bs[k][tx * TN + 4];
#pragma unroll
            for (int i = 0; i < TM; i++)
#pragma unroll
                for (int j = 0; j < TN; j++)
                    acc[i][j] = fmaf(a[i], b[j], acc[i][j]);
        }

        // split-K / slab boundary: fold slab chain into the running total
        // with a plain fp32 add (slice-order ascending) and restart chain.
        if (((k0 + BK) % kc) == 0) {
#pragma unroll
            for (int i = 0; i < TM; i++)
#pragma unroll
                for (int j = 0; j < TN; j++) {
                    tot[i][j] = __fadd_rn(tot[i][j], acc[i][j]);
                    acc[i][j] = 0.f;
                }
        }
    }
    // final (possibly partial) slab
#pragma unroll
    for (int i = 0; i < TM; i++)
#pragma unroll
        for (int j = 0; j < TN; j++)
            tot[i][j] = __fadd_rn(tot[i][j], acc[i][j]);

    const int row0 = m0 + ty * TM;
    const int col0 = n0 + tx * TN;

#pragma unroll
    for (int i = 0; i < TM; i++) {
        const int r = row0 + i;
        if (EPI == 0) {
            *(float4*)&ea.out[(size_t)r * N + col0]     = *(float4*)&tot[i][0];
            *(float4*)&ea.out[(size_t)r * N + col0 + 4] = *(float4*)&tot[i][4];
        } else if (EPI == 1) {
#pragma unroll
            for (int j = 0; j < TN; j++) {
                const size_t idx = (size_t)r * N + col0 + j;
                // acts = relu(xW + rec); acts = relu(acts - 0.5*(1 - gaba + glu))
                float v = __fadd_rn(tot[i][j], ea.e0[idx]);
                v = fmaxf(v, 0.f);
                const float t1  = __fsub_rn(1.0f, ea.e1[idx]);   // 1 - gaba
                const float t2  = __fadd_rn(t1, ea.e2[idx]);     // + glutamate
                const float thr = __fmul_rn(0.5f, t2);
                ea.out[idx] = fmaxf(__fsub_rn(v, thr), 0.f);
            }
        } else if (EPI == 2) {
            const float mx    = ea.e1[r];
            const float sum   = ea.e1[D_DIM + r];
            const float decay = ea.e2[r];
#pragma unroll
            for (int j = 0; j < TN; j++) {
                const size_t idx = (size_t)r * N + col0 + j;
                const float w   = ea.e0[idx];
                // w_sm = exp(w - mx) / sum   (division, as jax.nn.softmax)
                const float wsm = __fdiv_rn(expf(__fsub_rn(w, mx)), sum);
                // M = acc / 256 (exact); delta = w_sm * M
                const float Mv    = __fmul_rn(tot[i][j], 0.00390625f);
                const float delta = __fmul_rn(wsm, Mv);
                // (W + delta) - decay*W   (jax association)
                const float s1 = __fadd_rn(w, delta);
                const float s2 = __fmul_rn(decay, w);
                ea.out[idx] = __fsub_rn(s1, s2);
            }
        } else if (EPI == 3) {
#pragma unroll
            for (int j = 0; j < TN; j++) {
                const float v = __fadd_rn(tot[i][j], ea.e0[col0 + j]);
                ea.out[(size_t)r * N + col0 + j] = fmaxf(v, 0.f);
            }
        } else if (EPI == 4) {
#pragma unroll
            for (int g = 0; g < 2; g++) {
                const int c0 = col0 + 4 * g;          // aligned group of 4
                float t[4];
#pragma unroll
                for (int q = 0; q < 4; q++)
                    t[q] = tanhf(__fadd_rn(tot[i][4 * g + q], ea.e0[c0 + q]));
                const int d = c0 >> 2;
                const float inv = __fdiv_rn(1.0f, fmaxf(fabsf(t[1]), 1e-6f));
                const size_t src = (size_t)r * D_DIM + d;
                ea.out[(size_t)(1 * B_DIM + r) * D_DIM + d] =
                    __fadd_rn(ea.e1[src], __fmul_rn(t[0], inv));   // dop
                ea.out[(size_t)(2 * B_DIM + r) * D_DIM + d] =
                    __fadd_rn(ea.e2[src], t[1]);                   // ser
                ea.out[(size_t)(3 * B_DIM + r) * D_DIM + d] =
                    __fadd_rn(ea.e3[src], __fmul_rn(t[2], inv));   // glu
                ea.out[(size_t)(4 * B_DIM + r) * D_DIM + d] =
                    __fadd_rn(ea.e4[src], __fmul_rn(t[3], inv));   // gab
            }
        }
    }
}

// ------------- row softmax over [rows, 4096], one block per row -------------
__global__ void softmax_rows_kernel(const float* __restrict__ in,
                                    float* __restrict__ out)
{
    const int row = blockIdx.x;
    const int t   = threadIdx.x;            // 256 threads
    const float* x = in + (size_t)row * D_DIM;
    float v[16];
    float mx = -3.402823e38f;
#pragma unroll
    for (int i = 0; i < 16; i++) { v[i] = x[t + i * 256]; mx = fmaxf(mx, v[i]); }

    __shared__ float red[256];
    red[t] = mx; __syncthreads();
    for (int s = 128; s > 0; s >>= 1) {
        if (t < s) red[t] = fmaxf(red[t], red[t + s]);
        __syncthreads();
    }
    const float m = red[0]; __syncthreads();

    float s = 0.f;
#pragma unroll
    for (int i = 0; i < 16; i++) { v[i] = expf(__fsub_rn(v[i], m)); s = __fadd_rn(s, v[i]); }
    red[t] = s; __syncthreads();
    for (int st = 128; st > 0; st >>= 1) {
        if (t < st) red[t] = __fadd_rn(red[t], red[t + st]);
        __syncthreads();
    }
    const float den = red[0];
#pragma unroll
    for (int i = 0; i < 16; i++)
        out[(size_t)row * D_DIM + t + i * 256] = __fdiv_rn(v[i], den);
}

// ------------- per-row max & sum(exp(x-max)) for a [4096,4096] matrix -------
__global__ void rowstats_kernel(const float* __restrict__ in,
                                float* __restrict__ stats)
{
    const int row = blockIdx.x;
    const int t   = threadIdx.x;
    const float* x = in + (size_t)row * D_DIM;
    float v[16];
    float mx = -3.402823e38f;
#pragma unroll
    for (int i = 0; i < 16; i++) { v[i] = x[t + i * 256]; mx = fmaxf(mx, v[i]); }

    __shared__ float red[256];
    red[t] = mx; __syncthreads();
    for (int s = 128; s > 0; s >>= 1) {
        if (t < s) red[t] = fmaxf(red[t], red[t + s]);
        __syncthreads();
    }
    const float m = red[0]; __syncthreads();

    float s = 0.f;
#pragma unroll
    for (int i = 0; i < 16; i++) s = __fadd_rn(s, expf(__fsub_rn(v[i], m)));
    red[t] = s; __syncthreads();
    for (int st = 128; st > 0; st >>= 1) {
        if (t < st) red[t] = __fadd_rn(red[t], red[t + st]);
        __syncthreads();
    }
    if (t == 0) { stats[row] = m; stats[D_DIM + row] = red[0]; }
}

// ------------- mod = (alpha[j] * dopamine) * serotonin ----------------------
__global__ void mod_kernel(const float* __restrict__ alpha,
                           const float* __restrict__ dop,
                           const float* __restrict__ ser,
                           float* __restrict__ out)
{
    const int i = blockIdx.x * blockDim.x + threadIdx.x;
    const int j = i & (D_DIM - 1);
    out[i] = __fmul_rn(__fmul_rn(alpha[j], dop[i]), ser[i]);
}

// ----------------------------------------------------------------------------
extern "C" void kernel_launch(void* const* d_in, const int* in_sizes, int n_in,
                              void* d_out, int out_size)
{
    const float* x      = (const float*)d_in[0];
    const float* W      = (const float*)d_in[1];
    const float* RW     = (const float*)d_in[2];
    const float* alpha  = (const float*)d_in[3];
    const float* decay  = (const float*)d_in[4];
    const float* dop    = (const float*)d_in[5];
    const float* ser    = (const float*)d_in[6];
    const float* glu    = (const float*)d_in[7];
    const float* gab    = (const float*)d_in[8];
    const float* prev   = (const float*)d_in[9];
    const float* W1     = (const float*)d_in[10];
    const float* b1     = (const float*)d_in[11];
    const float* W2     = (const float*)d_in[12];
    const float* b2     = (const float*)d_in[13];
    float* out = (float*)d_out;

    float *p_rec, *p_asm_a, *p_asm_r, *p_mod, *p_hid, *p_stW, *p_stRW;
    cudaGetSymbolAddress((void**)&p_rec,   g_recurrent);
    cudaGetSymbolAddress((void**)&p_asm_a, g_asm_act);
    cudaGetSymbolAddress((void**)&p_asm_r, g_asm_rec);
    cudaGetSymbolAddress((void**)&p_mod,   g_mod);
    cudaGetSymbolAddress((void**)&p_hid,   g_hidden);
    cudaGetSymbolAddress((void**)&p_stW,   g_statsW);
    cudaGetSymbolAddress((void**)&p_stRW,  g_statsRW);

    float* acts_out = out;                                        // rows 0..255
    float* Wnew_out = out + (size_t)5 * B_DIM * D_DIM;            // rows 1280..
    float* RWnew_out = Wnew_out + (size_t)D_DIM * D_DIM;          // rows 5376..

    const dim3 blk(256);

    // All four K=4096 forward GEMMs use deterministic split-K=2 ordering
    // (two ascending 2048-chains, partials summed in slice order) — this
    // matched the reference for the 256x4096x4096 trio in round 10, and the
    // residual error pattern says hidden@W2 uses the same config.
    const int KC_SPLIT2 = 2048;

    // 1. recurrent = prev @ RW
    {
        EpiArgs ea{nullptr, nullptr, nullptr, nullptr, nullptr, p_rec};
        sgemm_kernel<0, 0><<<dim3(D_DIM / 128, B_DIM / 64), blk>>>(
            prev, RW, B_DIM, D_DIM, D_DIM, KC_SPLIT2, ea);
    }
    // 2. acts = relu(relu(x@W + rec) - thr) -> d_out rows 0..255
    {
        EpiArgs ea{p_rec, gab, glu, nullptr, nullptr, acts_out};
        sgemm_kernel<0, 1><<<dim3(D_DIM / 128, B_DIM / 64), blk>>>(
            x, W, B_DIM, D_DIM, D_DIM, KC_SPLIT2, ea);
    }
    // 3. mod
    mod_kernel<<<(B_DIM * D_DIM) / 256, blk>>>(alpha, dop, ser, p_mod);
    // 4/5. row softmax of acts and recurrent
    softmax_rows_kernel<<<B_DIM, blk>>>(acts_out, p_asm_a);
    softmax_rows_kernel<<<B_DIM, blk>>>(p_rec, p_asm_r);
    // 6/7. row stats of W and RW
    rowstats_kernel<<<D_DIM, blk>>>(W,  p_stW);
    rowstats_kernel<<<D_DIM, blk>>>(RW, p_stRW);
    // 8. W_new  = (W + softmax(W)*(a_sm_act^T @ mod)/B) - decay*W
    {
        EpiArgs ea{W, p_stW, decay, nullptr, nullptr, Wnew_out};
        sgemm_kernel<1, 2><<<dim3(D_DIM / 128, D_DIM / 64), blk>>>(
            p_asm_a, p_mod, D_DIM, D_DIM, B_DIM, 256, ea);
    }
    // 9. RW_new
    {
        EpiArgs ea{RW, p_stRW, decay, nullptr, nullptr, RWnew_out};
        sgemm_kernel<1, 2><<<dim3(D_DIM / 128, D_DIM / 64), blk>>>(
            p_asm_r, p_mod, D_DIM, D_DIM, B_DIM, 256, ea);
    }
    // 10. hidden = relu(acts @ W1 + b1)
    {
        EpiArgs ea{b1, nullptr, nullptr, nullptr, nullptr, p_hid};
        sgemm_kernel<0, 3><<<dim3(D_DIM / 128, B_DIM / 64), blk>>>(
            acts_out, W1, B_DIM, D_DIM, D_DIM, KC_SPLIT2, ea);
    }
    // 11. h = tanh(hidden @ W2 + b2) -> neuromodulator scatter
    {
        EpiArgs ea{b2, dop, ser, glu, gab, out};
        sgemm_kernel<0, 4><<<dim3(D4 / 128, B_DIM / 64), blk>>>(
            p_hid, W2, B_DIM, D4, D_DIM, KC_SPLIT2, ea);
    }
}

// round 15
// speedup vs baseline: 3.0350x; 3.0350x over previous
#include <cuda_runtime.h>
#include <cstddef>

#define B_DIM 256
#define D_DIM 4096
#define D4    (4 * D_DIM)

typedef unsigned long long ull;

// ---------------- scratch (static __device__ globals; no allocation) --------
__device__ float g_part    [2 * B_DIM * D4];   // 32 MB split-K partials (max: W2)
__device__ float g_recurrent[B_DIM * D_DIM];   // 4 MB
__device__ float g_asm_act [B_DIM * D_DIM];    // 4 MB
__device__ float g_asm_rec [B_DIM * D_DIM];    // 4 MB
__device__ float g_mod     [B_DIM * D_DIM];    // 4 MB
__device__ float g_hidden  [B_DIM * D_DIM];    // 4 MB
__device__ float g_statsW  [2 * D_DIM];        // rowmax, rowsumexp
__device__ float g_statsRW [2 * D_DIM];

// ---------------- packed fp32x2 helpers (lane-wise IEEE RN fp32 FMA) --------
__device__ __forceinline__ ull pack2dup(float x) {
    ull r; asm("mov.b64 %0, {%1, %1};" : "=l"(r) : "f"(x)); return r;
}
__device__ __forceinline__ void fma2(ull& d, ull a, ull b) {
    asm("fma.rn.f32x2 %0, %1, %2, %0;" : "+l"(d) : "l"(a), "l"(b));
}
__device__ __forceinline__ void unpack2(ull v, float& lo, float& hi) {
    asm("mov.b64 {%0, %1}, %2;" : "=f"(lo), "=f"(hi) : "l"(v));
}

// ============================================================================
// Forward GEMM: C_partial[z] = A[M,K(row-major)] @ B[K,N], k in [z*K/2,(z+1)*K/2)
// Per output element: pure ascending-k fp32 FMA chain (bit-exact split-K=2 slab).
// grid = (N/128, M/64, 2)
// ============================================================================
__global__ void __launch_bounds__(256, 2)
fwd_gemm_kernel(const float* __restrict__ A, const float* __restrict__ Bm,
                float* __restrict__ P, int M, int N, int K)
{
    constexpr int BM = 64, BN = 128, BK = 16;
    __shared__ float As[2][BK][BM];
    __shared__ float Bs[2][BK][BN];

    const int tid = threadIdx.x;
    const int tx  = tid & 15;             // col-group selector
    const int ty  = tid >> 4;             // row-group selector (0..15)
    const int n0  = blockIdx.x * BN;
    const int m0  = blockIdx.y * BM;
    const int kh  = K >> 1;
    const int kbeg   = blockIdx.z * kh;
    const int ktiles = kh / BK;

    const int a_r = tid >> 2, a_c = (tid & 3) * 4;   // A loader: 64x16 tile
    const int b_r = tid >> 5, b_c = (tid & 31) * 4;  // B loader: 16x128 tile

    const float* Aptr = A + (size_t)(m0 + a_r) * K + kbeg + a_c;
    const float* Bptr = Bm + (size_t)(kbeg + b_r) * N + n0 + b_c;

    ull acc[4][4];                        // 4 rows x 4 col-pairs (8 cols)
#pragma unroll
    for (int i = 0; i < 4; i++)
#pragma unroll
        for (int j = 0; j < 4; j++) acc[i][j] = 0ull;

    // preload tile 0
    float4 av  = *(const float4*)Aptr;
    float4 bv0 = *(const float4*)Bptr;
    float4 bv1 = *(const float4*)(Bptr + (size_t)8 * N);
    As[0][a_c + 0][a_r] = av.x;
    As[0][a_c + 1][a_r] = av.y;
    As[0][a_c + 2][a_r] = av.z;
    As[0][a_c + 3][a_r] = av.w;
    *(float4*)&Bs[0][b_r][b_c]     = bv0;
    *(float4*)&Bs[0][b_r + 8][b_c] = bv1;
    __syncthreads();

    int buf = 0;
    for (int t = 0; t < ktiles; ++t) {
        if (t + 1 < ktiles) {
            av  = *(const float4*)(Aptr + (t + 1) * BK);
            bv0 = *(const float4*)(Bptr + (size_t)(t + 1) * BK * N);
            bv1 = *(const float4*)(Bptr + (size_t)((t + 1) * BK + 8) * N);
        }
#pragma unroll
        for (int k = 0; k < BK; k++) {
            float a4[4];
            *(float4*)a4 = *(const float4*)&As[buf][k][ty * 4];
            const ull b0 = *(const ull*)&Bs[buf][k][tx * 4];
            const ull b1 = *(const ull*)&Bs[buf][k][tx * 4 + 2];
            const ull b2 = *(const ull*)&Bs[buf][k][64 + tx * 4];
            const ull b3 = *(const ull*)&Bs[buf][k][64 + tx * 4 + 2];
#pragma unroll
            for (int i = 0; i < 4; i++) {
                const ull a2 = pack2dup(a4[i]);
                fma2(acc[i][0], a2, b0);
                fma2(acc[i][1], a2, b1);
                fma2(acc[i][2], a2, b2);
                fma2(acc[i][3], a2, b3);
            }
        }
        if (t + 1 < ktiles) {
            const int nb = buf ^ 1;
            As[nb][a_c + 0][a_r] = av.x;
            As[nb][a_c + 1][a_r] = av.y;
            As[nb][a_c + 2][a_r] = av.z;
            As[nb][a_c + 3][a_r] = av.w;
            *(float4*)&Bs[nb][b_r][b_c]     = bv0;
            *(float4*)&Bs[nb][b_r + 8][b_c] = bv1;
            __syncthreads();
        }
        buf ^= 1;
    }

    // write partial slab
    float* Pz = P + (size_t)blockIdx.z * M * N;
    const int rA = m0 + ty * 4;
    const int cA = n0 + tx * 4;
    const int cB = cA + 64;
#pragma unroll
    for (int i = 0; i < 4; i++) {
        const size_t off = (size_t)(rA + i) * N;
        *(ull*)&Pz[off + cA]     = acc[i][0];
        *(ull*)&Pz[off + cA + 2] = acc[i][1];
        *(ull*)&Pz[off + cB]     = acc[i][2];
        *(ull*)&Pz[off + cB + 2] = acc[i][3];
    }
}

// ============================================================================
// Hebbian GEMM (single K=256 slab, fused epilogue):
//   out[r,c] = (W[r,c] + softmax(W)[r,c] * (a_sm^T@mod)[r,c]/256) - decay[r]*W[r,c]
// A is a_sm stored [K=256, M=4096] (logical A^T), B is mod [K=256, N=4096].
// grid = (N/128, M/64)
// ============================================================================
__global__ void __launch_bounds__(256, 2)
hebb_gemm_kernel(const float* __restrict__ A, const float* __restrict__ Bm,
                 const float* __restrict__ Wmat, const float* __restrict__ stats,
                 const float* __restrict__ decay, float* __restrict__ out)
{
    constexpr int BM = 64, BN = 128, BK = 16, K = B_DIM, N = D_DIM, MROW = D_DIM;
    __shared__ float As[2][BK][BM];
    __shared__ float Bs[2][BK][BN];

    const int tid = threadIdx.x;
    const int tx  = tid & 15;
    const int ty  = tid >> 4;
    const int n0  = blockIdx.x * BN;
    const int m0  = blockIdx.y * BM;
    constexpr int ktiles = K / BK;        // 16

    const int at_r = tid >> 4, at_c = (tid & 15) * 4;   // A loader: [k, m] tile
    const int b_r  = tid >> 5, b_c  = (tid & 31) * 4;

    const float* Aptr = A + (size_t)at_r * MROW + m0 + at_c;
    const float* Bptr = Bm + (size_t)b_r * N + n0 + b_c;

    ull acc[4][4];
#pragma unroll
    for (int i = 0; i < 4; i++)
#pragma unroll
        for (int j = 0; j < 4; j++) acc[i][j] = 0ull;

    float4 av  = *(const float4*)Aptr;
    float4 bv0 = *(const float4*)Bptr;
    float4 bv1 = *(const float4*)(Bptr + (size_t)8 * N);
    *(float4*)&As[0][at_r][at_c]   = av;
    *(float4*)&Bs[0][b_r][b_c]     = bv0;
    *(float4*)&Bs[0][b_r + 8][b_c] = bv1;
    __syncthreads();

    int buf = 0;
    for (int t = 0; t < ktiles; ++t) {
        if (t + 1 < ktiles) {
            av  = *(const float4*)(Aptr + (size_t)(t + 1) * BK * MROW);
            bv0 = *(const float4*)(Bptr + (size_t)(t + 1) * BK * N);
            bv1 = *(const float4*)(Bptr + (size_t)((t + 1) * BK + 8) * N);
        }
#pragma unroll
        for (int k = 0; k < BK; k++) {
            float a4[4];
            *(float4*)a4 = *(const float4*)&As[buf][k][ty * 4];
            const ull b0 = *(const ull*)&Bs[buf][k][tx * 4];
            const ull b1 = *(const ull*)&Bs[buf][k][tx * 4 + 2];
            const ull b2 = *(const ull*)&Bs[buf][k][64 + tx * 4];
            const ull b3 = *(const ull*)&Bs[buf][k][64 + tx * 4 + 2];
#pragma unroll
            for (int i = 0; i < 4; i++) {
                const ull a2 = pack2dup(a4[i]);
                fma2(acc[i][0], a2, b0);
                fma2(acc[i][1], a2, b1);
                fma2(acc[i][2], a2, b2);
                fma2(acc[i][3], a2, b3);
            }
        }
        if (t + 1 < ktiles) {
            const int nb = buf ^ 1;
            *(float4*)&As[nb][at_r][at_c]   = av;
            *(float4*)&Bs[nb][b_r][b_c]     = bv0;
            *(float4*)&Bs[nb][b_r + 8][b_c] = bv1;
            __syncthreads();
        }
        buf ^= 1;
    }

    const int rA = m0 + ty * 4;
    const int cA = n0 + tx * 4;
    const int cB = cA + 64;
#pragma unroll
    for (int i = 0; i < 4; i++) {
        const int r = rA + i;
        const float mx  = stats[r];
        const float sum = stats[D_DIM + r];
        const float dec = decay[r];
        float v[8];
        unpack2(acc[i][0], v[0], v[1]);
        unpack2(acc[i][1], v[2], v[3]);
        unpack2(acc[i][2], v[4], v[5]);
        unpack2(acc[i][3], v[6], v[7]);
#pragma unroll
        for (int j = 0; j < 8; j++) {
            const int c = (j < 4) ? (cA + j) : (cB + j - 4);
            const size_t idx = (size_t)r * N + c;
            const float w   = Wmat[idx];
            const float wsm = __fdiv_rn(expf(__fsub_rn(w, mx)), sum);
            const float Mv    = __fmul_rn(v[j], 0.00390625f);
            const float delta = __fmul_rn(wsm, Mv);
            const float s1 = __fadd_rn(w, delta);
            const float s2 = __fmul_rn(dec, w);
            out[idx] = __fsub_rn(s1, s2);
        }
    }
}

// ============================================================================
// Combine kernels: tot = slab0 + slab1 (ordered __fadd_rn), then epilogue.
// ============================================================================
__global__ void combine_store_kernel(const float* __restrict__ P,
                                     float* __restrict__ out, int n)
{
    const int i = (blockIdx.x * blockDim.x + threadIdx.x) * 4;
    const float4 p0 = *(const float4*)&P[i];
    const float4 p1 = *(const float4*)&P[n + i];
    float4 r;
    r.x = __fadd_rn(p0.x, p1.x);
    r.y = __fadd_rn(p0.y, p1.y);
    r.z = __fadd_rn(p0.z, p1.z);
    r.w = __fadd_rn(p0.w, p1.w);
    *(float4*)&out[i] = r;
}

__global__ void combine_acts_kernel(const float* __restrict__ P,
                                    const float* __restrict__ rec,
                                    const float* __restrict__ gab,
                                    const float* __restrict__ glu,
                                    float* __restrict__ out, int n)
{
    const int i = (blockIdx.x * blockDim.x + threadIdx.x) * 4;
    const float4 p0 = *(const float4*)&P[i];
    const float4 p1 = *(const float4*)&P[n + i];
    const float4 rc = *(const float4*)&rec[i];
    const float4 gb = *(const float4*)&gab[i];
    const float4 gl = *(const float4*)&glu[i];
    float tot[4] = {__fadd_rn(p0.x, p1.x), __fadd_rn(p0.y, p1.y),
                    __fadd_rn(p0.z, p1.z), __fadd_rn(p0.w, p1.w)};
    const float rcv[4] = {rc.x, rc.y, rc.z, rc.w};
    const float gbv[4] = {gb.x, gb.y, gb.z, gb.w};
    const float glv[4] = {gl.x, gl.y, gl.z, gl.w};
    float o[4];
#pragma unroll
    for (int q = 0; q < 4; q++) {
        float v = __fadd_rn(tot[q], rcv[q]);
        v = fmaxf(v, 0.f);
        const float t1  = __fsub_rn(1.0f, gbv[q]);
        const float t2  = __fadd_rn(t1, glv[q]);
        const float thr = __fmul_rn(0.5f, t2);
        o[q] = fmaxf(__fsub_rn(v, thr), 0.f);
    }
    *(float4*)&out[i] = make_float4(o[0], o[1], o[2], o[3]);
}

__global__ void combine_biasrelu_kernel(const float* __restrict__ P,
                                        const float* __restrict__ b1,
                                        float* __restrict__ out, int n)
{
    const int i = (blockIdx.x * blockDim.x + threadIdx.x) * 4;
    const float4 p0 = *(const float4*)&P[i];
    const float4 p1 = *(const float4*)&P[n + i];
    const float4 bb = *(const float4*)&b1[i & (D_DIM - 1)];
    float4 r;
    r.x = fmaxf(__fadd_rn(__fadd_rn(p0.x, p1.x), bb.x), 0.f);
    r.y = fmaxf(__fadd_rn(__fadd_rn(p0.y, p1.y), bb.y), 0.f);
    r.z = fmaxf(__fadd_rn(__fadd_rn(p0.z, p1.z), bb.z), 0.f);
    r.w = fmaxf(__fadd_rn(__fadd_rn(p0.w, p1.w), bb.w), 0.f);
    *(float4*)&out[i] = r;
}

__global__ void combine_neuro_kernel(const float* __restrict__ P,
                                     const float* __restrict__ b2,
                                     const float* __restrict__ dop,
                                     const float* __restrict__ ser,
                                     const float* __restrict__ glu,
                                     const float* __restrict__ gab,
                                     float* __restrict__ out)
{
    const int gid = blockIdx.x * blockDim.x + threadIdx.x;  // one 4-col group
    const int r = gid >> 12;                 // / D_DIM groups per row
    const int d = gid & (D_DIM - 1);
    const size_t base = (size_t)r * D4 + d * 4;
    const float4 p0 = *(const float4*)&P[base];
    const float4 p1 = *(const float4*)&P[(size_t)B_DIM * D4 + base];
    const float4 bb = *(const float4*)&b2[d * 4];
    float t[4];
    t[0] = tanhf(__fadd_rn(__fadd_rn(p0.x, p1.x), bb.x));
    t[1] = tanhf(__fadd_rn(__fadd_rn(p0.y, p1.y), bb.y));
    t[2] = tanhf(__fadd_rn(__fadd_rn(p0.z, p1.z), bb.z));
    t[3] = tanhf(__fadd_rn(__fadd_rn(p0.w, p1.w), bb.w));
    const float inv = __fdiv_rn(1.0f, fmaxf(fabsf(t[1]), 1e-6f));
    const size_t src = (size_t)r * D_DIM + d;
    out[(size_t)(1 * B_DIM + r) * D_DIM + d] = __fadd_rn(dop[src], __fmul_rn(t[0], inv));
    out[(size_t)(2 * B_DIM + r) * D_DIM + d] = __fadd_rn(ser[src], t[1]);
    out[(size_t)(3 * B_DIM + r) * D_DIM + d] = __fadd_rn(glu[src], __fmul_rn(t[2], inv));
    out[(size_t)(4 * B_DIM + r) * D_DIM + d] = __fadd_rn(gab[src], __fmul_rn(t[3], inv));
}

// ------------- row softmax over [rows, 4096], one block per row -------------
__global__ void softmax_rows_kernel(const float* __restrict__ in,
                                    float* __restrict__ out)
{
    const int row = blockIdx.x;
    const int t   = threadIdx.x;            // 256 threads
    const float* x = in + (size_t)row * D_DIM;
    float v[16];
    float mx = -3.402823e38f;
#pragma unroll
    for (int i = 0; i < 16; i++) { v[i] = x[t + i * 256]; mx = fmaxf(mx, v[i]); }

    __shared__ float red[256];
    red[t] = mx; __syncthreads();
    for (int s = 128; s > 0; s >>= 1) {
        if (t < s) red[t] = fmaxf(red[t], red[t + s]);
        __syncthreads();
    }
    const float m = red[0]; __syncthreads();

    float s = 0.f;
#pragma unroll
    for (int i = 0; i < 16; i++) { v[i] = expf(__fsub_rn(v[i], m)); s = __fadd_rn(s, v[i]); }
    red[t] = s; __syncthreads();
    for (int st = 128; st > 0; st >>= 1) {
        if (t < st) red[t] = __fadd_rn(red[t], red[t + st]);
        __syncthreads();
    }
    const float den = red[0];
#pragma unroll
    for (int i = 0; i < 16; i++)
        out[(size_t)row * D_DIM + t + i * 256] = __fdiv_rn(v[i], den);
}

// ------------- per-row max & sum(exp(x-max)) for a [4096,4096] matrix -------
__global__ void rowstats_kernel(const float* __restrict__ in,
                                float* __restrict__ stats)
{
    const int row = blockIdx.x;
    const int t   = threadIdx.x;
    const float* x = in + (size_t)row * D_DIM;
    float v[16];
    float mx = -3.402823e38f;
#pragma unroll
    for (int i = 0; i < 16; i++) { v[i] = x[t + i * 256]; mx = fmaxf(mx, v[i]); }

    __shared__ float red[256];
    red[t] = mx; __syncthreads();
    for (int s = 128; s > 0; s >>= 1) {
        if (t < s) red[t] = fmaxf(red[t], red[t + s]);
        __syncthreads();
    }
    const float m = red[0]; __syncthreads();

    float s = 0.f;
#pragma unroll
    for (int i = 0; i < 16; i++) s = __fadd_rn(s, expf(__fsub_rn(v[i], m)));
    red[t] = s; __syncthreads();
    for (int st = 128; st > 0; st >>= 1) {
        if (t < st) red[t] = __fadd_rn(red[t], red[t + st]);
        __syncthreads();
    }
    if (t == 0) { stats[row] = m; stats[D_DIM + row] = red[0]; }
}

// ------------- mod = (alpha[j] * dopamine) * serotonin ----------------------
__global__ void mod_kernel(const float* __restrict__ alpha,
                           const float* __restrict__ dop,
                           const float* __restrict__ ser,
                           float* __restrict__ out)
{
    const int i = blockIdx.x * blockDim.x + threadIdx.x;
    const int j = i & (D_DIM - 1);
    out[i] = __fmul_rn(__fmul_rn(alpha[j], dop[i]), ser[i]);
}

// ----------------------------------------------------------------------------
extern "C" void kernel_launch(void* const* d_in, const int* in_sizes, int n_in,
                              void* d_out, int out_size)
{
    const float* x      = (const float*)d_in[0];
    const float* W      = (const float*)d_in[1];
    const float* RW     = (const float*)d_in[2];
    const float* alpha  = (const float*)d_in[3];
    const float* decay  = (const float*)d_in[4];
    const float* dop    = (const float*)d_in[5];
    const float* ser    = (const float*)d_in[6];
    const float* glu    = (const float*)d_in[7];
    const float* gab    = (const float*)d_in[8];
    const float* prev   = (const float*)d_in[9];
    const float* W1     = (const float*)d_in[10];
    const float* b1     = (const float*)d_in[11];
    const float* W2     = (const float*)d_in[12];
    const float* b2     = (const float*)d_in[13];
    float* out = (float*)d_out;

    float *p_part, *p_rec, *p_asm_a, *p_asm_r, *p_mod, *p_hid, *p_stW, *p_stRW;
    cudaGetSymbolAddress((void**)&p_part,  g_part);
    cudaGetSymbolAddress((void**)&p_rec,   g_recurrent);
    cudaGetSymbolAddress((void**)&p_asm_a, g_asm_act);
    cudaGetSymbolAddress((void**)&p_asm_r, g_asm_rec);
    cudaGetSymbolAddress((void**)&p_mod,   g_mod);
    cudaGetSymbolAddress((void**)&p_hid,   g_hidden);
    cudaGetSymbolAddress((void**)&p_stW,   g_statsW);
    cudaGetSymbolAddress((void**)&p_stRW,  g_statsRW);

    float* acts_out  = out;                                       // rows 0..255
    float* Wnew_out  = out + (size_t)5 * B_DIM * D_DIM;
    float* RWnew_out = Wnew_out + (size_t)D_DIM * D_DIM;

    const dim3 blk(256);
    const dim3 grid_fwd(D_DIM / 128, B_DIM / 64, 2);     // trio forward GEMMs
    const dim3 grid_w2(D4 / 128, B_DIM / 64, 2);         // hidden @ W2
    const dim3 grid_hebb(D_DIM / 128, D_DIM / 64);
    const int  nBD = B_DIM * D_DIM;                      // 1M elements
    const int  cmb_blocks = nBD / (256 * 4);             // float4 combines

    // 1. recurrent = prev @ RW   (split-K=2 partials -> ordered combine)
    fwd_gemm_kernel<<<grid_fwd, blk>>>(prev, RW, p_part, B_DIM, D_DIM, D_DIM);
    combine_store_kernel<<<cmb_blocks, blk>>>(p_part, p_rec, nBD);

    // 2. acts = relu(relu(x@W + rec) - thr) -> d_out rows 0..255
    fwd_gemm_kernel<<<grid_fwd, blk>>>(x, W, p_part, B_DIM, D_DIM, D_DIM);
    combine_acts_kernel<<<cmb_blocks, blk>>>(p_part, p_rec, gab, glu, acts_out, nBD);

    // 3. mod
    mod_kernel<<<nBD / 256, blk>>>(alpha, dop, ser, p_mod);

    // 4/5. row softmax of acts and recurrent
    softmax_rows_kernel<<<B_DIM, blk>>>(acts_out, p_asm_a);
    softmax_rows_kernel<<<B_DIM, blk>>>(p_rec, p_asm_r);

    // 6/7. row stats of W and RW
    rowstats_kernel<<<D_DIM, blk>>>(W,  p_stW);
    rowstats_kernel<<<D_DIM, blk>>>(RW, p_stRW);

    // 8/9. Hebbian updates (K=256 single-slab, fused epilogue)
    hebb_gemm_kernel<<<grid_hebb, blk>>>(p_asm_a, p_mod, W,  p_stW,  decay, Wnew_out);
    hebb_gemm_kernel<<<grid_hebb, blk>>>(p_asm_r, p_mod, RW, p_stRW, decay, RWnew_out);

    // 10. hidden = relu(acts @ W1 + b1)
    fwd_gemm_kernel<<<grid_fwd, blk>>>(acts_out, W1, p_part, B_DIM, D_DIM, D_DIM);
    combine_biasrelu_kernel<<<cmb_blocks, blk>>>(p_part, b1, p_hid, nBD);

    // 11. h = tanh(hidden @ W2 + b2) -> neuromodulator scatter
    fwd_gemm_kernel<<<grid_w2, blk>>>(p_hid, W2, p_part, B_DIM, D4, D_DIM);
    combine_neuro_kernel<<<nBD / 256, blk>>>(p_part, b2, dop, ser, glu, gab, out);
}

// round 16
// speedup vs baseline: 3.4677x; 1.1426x over previous
#include <cuda_runtime.h>
#include <cuda_bf16.h>
#include <cstddef>
#include <cstdint>

#define B_DIM 256
#define D_DIM 4096
#define D4    (4 * D_DIM)

typedef unsigned long long ull;

// ---------------- scratch (static __device__ globals; no allocation) --------
__device__ float g_part    [2 * B_DIM * D4];   // 32 MB split-K partials (max: W2)
__device__ float g_recurrent[B_DIM * D_DIM];   // 4 MB
__device__ float g_asm_act [B_DIM * D_DIM];    // 4 MB
__device__ float g_asm_rec [B_DIM * D_DIM];    // 4 MB
__device__ float g_mod     [B_DIM * D_DIM];    // 4 MB
__device__ float g_hidden  [B_DIM * D_DIM];    // 4 MB
__device__ float g_statsW  [2 * D_DIM];        // rowmax, rowsumexp
__device__ float g_statsRW [2 * D_DIM];

// ---------------- packed fp32x2 helpers (lane-wise IEEE RN fp32 FMA) --------
__device__ __forceinline__ ull pack2dup(float x) {
    ull r; asm("mov.b64 %0, {%1, %1};" : "=l"(r) : "f"(x)); return r;
}
__device__ __forceinline__ void fma2(ull& d, ull a, ull b) {
    asm("fma.rn.f32x2 %0, %1, %2, %0;" : "+l"(d) : "l"(a), "l"(b));
}

__device__ __forceinline__ uint32_t cvta_smem(const void* p) {
    uint32_t a;
    asm("{ .reg .u64 t; cvta.to.shared.u64 t, %1; cvt.u32.u64 %0, t; }"
        : "=r"(a) : "l"(p));
    return a;
}

// ============================================================================
// Forward GEMM (UNCHANGED from round 15 — bit-exact split-K=2 slabs, FFMA2)
// grid = (N/128, M/64, 2)
// ============================================================================
__global__ void __launch_bounds__(256, 2)
fwd_gemm_kernel(const float* __restrict__ A, const float* __restrict__ Bm,
                float* __restrict__ P, int M, int N, int K)
{
    constexpr int BM = 64, BN = 128, BK = 16;
    __shared__ float As[2][BK][BM];
    __shared__ float Bs[2][BK][BN];

    const int tid = threadIdx.x;
    const int tx  = tid & 15;
    const int ty  = tid >> 4;
    const int n0  = blockIdx.x * BN;
    const int m0  = blockIdx.y * BM;
    const int kh  = K >> 1;
    const int kbeg   = blockIdx.z * kh;
    const int ktiles = kh / BK;

    const int a_r = tid >> 2, a_c = (tid & 3) * 4;
    const int b_r = tid >> 5, b_c = (tid & 31) * 4;

    const float* Aptr = A + (size_t)(m0 + a_r) * K + kbeg + a_c;
    const float* Bptr = Bm + (size_t)(kbeg + b_r) * N + n0 + b_c;

    ull acc[4][4];
#pragma unroll
    for (int i = 0; i < 4; i++)
#pragma unroll
        for (int j = 0; j < 4; j++) acc[i][j] = 0ull;

    float4 av  = *(const float4*)Aptr;
    float4 bv0 = *(const float4*)Bptr;
    float4 bv1 = *(const float4*)(Bptr + (size_t)8 * N);
    As[0][a_c + 0][a_r] = av.x;
    As[0][a_c + 1][a_r] = av.y;
    As[0][a_c + 2][a_r] = av.z;
    As[0][a_c + 3][a_r] = av.w;
    *(float4*)&Bs[0][b_r][b_c]     = bv0;
    *(float4*)&Bs[0][b_r + 8][b_c] = bv1;
    __syncthreads();

    int buf = 0;
    for (int t = 0; t < ktiles; ++t) {
        if (t + 1 < ktiles) {
            av  = *(const float4*)(Aptr + (t + 1) * BK);
            bv0 = *(const float4*)(Bptr + (size_t)(t + 1) * BK * N);
            bv1 = *(const float4*)(Bptr + (size_t)((t + 1) * BK + 8) * N);
        }
#pragma unroll
        for (int k = 0; k < BK; k++) {
            float a4[4];
            *(float4*)a4 = *(const float4*)&As[buf][k][ty * 4];
            const ull b0 = *(const ull*)&Bs[buf][k][tx * 4];
            const ull b1 = *(const ull*)&Bs[buf][k][tx * 4 + 2];
            const ull b2 = *(const ull*)&Bs[buf][k][64 + tx * 4];
            const ull b3 = *(const ull*)&Bs[buf][k][64 + tx * 4 + 2];
#pragma unroll
            for (int i = 0; i < 4; i++) {
                const ull a2 = pack2dup(a4[i]);
                fma2(acc[i][0], a2, b0);
                fma2(acc[i][1], a2, b1);
                fma2(acc[i][2], a2, b2);
                fma2(acc[i][3], a2, b3);
            }
        }
        if (t + 1 < ktiles) {
            const int nb = buf ^ 1;
            As[nb][a_c + 0][a_r] = av.x;
            As[nb][a_c + 1][a_r] = av.y;
            As[nb][a_c + 2][a_r] = av.z;
            As[nb][a_c + 3][a_r] = av.w;
            *(float4*)&Bs[nb][b_r][b_c]     = bv0;
            *(float4*)&Bs[nb][b_r + 8][b_c] = bv1;
            __syncthreads();
        }
        buf ^= 1;
    }

    float* Pz = P + (size_t)blockIdx.z * M * N;
    const int rA = m0 + ty * 4;
    const int cA = n0 + tx * 4;
    const int cB = cA + 64;
#pragma unroll
    for (int i = 0; i < 4; i++) {
        const size_t off = (size_t)(rA + i) * N;
        *(ull*)&Pz[off + cA]     = acc[i][0];
        *(ull*)&Pz[off + cA + 2] = acc[i][1];
        *(ull*)&Pz[off + cB]     = acc[i][2];
        *(ull*)&Pz[off + cB + 2] = acc[i][3];
    }
}

// ============================================================================
// Hebbian GEMM via bf16 mma.sync (HMMA) + fused epilogue.
//   acc[i,j] = sum_b a_sm[b,i] * mod[b,j]   (M=N=4096, K=256, bf16 inputs)
//   out[r,c] = (W + softmax(W)*acc/256) - decay[r]*W
// CTA tile 128x128, 8 warps in 2(m) x 4(n), warp tile 64x32.
// smem: [k(16)][128] bf16 tiles (256B rows), 16B-chunk XOR swizzle.
// ============================================================================
__device__ __forceinline__ uint32_t hswz(uint32_t k, uint32_t c) {
    return k * 256u + ((((c >> 3) ^ (k & 7)) << 4) | ((c & 7) << 1));
}

__device__ __forceinline__ void sts_bf16x8(uint32_t addr, float4 v0, float4 v1) {
    __nv_bfloat162 p0 = __floats2bfloat162_rn(v0.x, v0.y);
    __nv_bfloat162 p1 = __floats2bfloat162_rn(v0.z, v0.w);
    __nv_bfloat162 p2 = __floats2bfloat162_rn(v1.x, v1.y);
    __nv_bfloat162 p3 = __floats2bfloat162_rn(v1.z, v1.w);
    uint32_t u0 = *(uint32_t*)&p0, u1 = *(uint32_t*)&p1;
    uint32_t u2 = *(uint32_t*)&p2, u3 = *(uint32_t*)&p3;
    asm volatile("st.shared.v4.b32 [%0], {%1,%2,%3,%4};"
                 :: "r"(addr), "r"(u0), "r"(u1), "r"(u2), "r"(u3) : "memory");
}

__device__ __forceinline__ void ldsm4t(uint32_t* r, uint32_t addr) {
    asm volatile("ldmatrix.sync.aligned.m8n8.x4.trans.shared.b16 {%0,%1,%2,%3}, [%4];"
                 : "=r"(r[0]), "=r"(r[1]), "=r"(r[2]), "=r"(r[3]) : "r"(addr));
}

__device__ __forceinline__ void mma_bf16(float* c, const uint32_t* a,
                                         uint32_t b0, uint32_t b1) {
    asm volatile(
        "mma.sync.aligned.m16n8k16.row.col.f32.bf16.bf16.f32 "
        "{%0,%1,%2,%3}, {%4,%5,%6,%7}, {%8,%9}, {%0,%1,%2,%3};"
        : "+f"(c[0]), "+f"(c[1]), "+f"(c[2]), "+f"(c[3])
        : "r"(a[0]), "r"(a[1]), "r"(a[2]), "r"(a[3]), "r"(b0), "r"(b1));
}

__global__ void __launch_bounds__(256)
hebb_mma_kernel(const float* __restrict__ Am, const float* __restrict__ Bm,
                const float* __restrict__ Wmat, const float* __restrict__ stats,
                const float* __restrict__ decay, float* __restrict__ out)
{
    __shared__ __align__(16) unsigned char sA[2][4096];
    __shared__ __align__(16) unsigned char sB[2][4096];
    const int tid  = threadIdx.x;
    const int lane = tid & 31;
    const int wid  = tid >> 5;
    const int mw   = wid >> 2;            // 0..1
    const int nw   = wid & 3;             // 0..3
    const uint32_t sAb = cvta_smem(sA);
    const uint32_t sBb = cvta_smem(sB);

    // loaders: 16 rows(k) x 128 cols, 8 floats per thread
    const int lr = tid >> 4;
    const int lc = (tid & 15) * 8;
    const float* gA = Am + (size_t)lr * D_DIM + blockIdx.y * 128 + lc;
    const float* gB = Bm + (size_t)lr * D_DIM + blockIdx.x * 128 + lc;
    const uint32_t stOff = hswz((uint32_t)lr, (uint32_t)lc);

    // ldmatrix.x4.trans lane-address offsets (tile-local, loop-invariant)
    const uint32_t arow  = ((lane >> 4) & 1) * 8 + (lane & 7);
    const uint32_t acolH = ((lane >> 3) & 1) * 8;
    uint32_t aOff[4];
#pragma unroll
    for (int mi = 0; mi < 4; mi++)
        aOff[mi] = hswz(arow, mw * 64 + mi * 16 + acolH);
    const uint32_t brow  = ((lane >> 3) & 1) * 8 + (lane & 7);
    const uint32_t bcolH = ((lane >> 4) & 1) * 8;
    uint32_t bOff[2];
#pragma unroll
    for (int nb = 0; nb < 2; nb++)
        bOff[nb] = hswz(brow, nw * 32 + nb * 16 + bcolH);

    float c[4][4][4];
#pragma unroll
    for (int mi = 0; mi < 4; mi++)
#pragma unroll
        for (int ni = 0; ni < 4; ni++)
#pragma unroll
            for (int q = 0; q < 4; q++) c[mi][ni][q] = 0.f;

    // prologue: tile 0
    {
        float4 a0 = *(const float4*)gA;
        float4 a1 = *(const float4*)(gA + 4);
        float4 b0 = *(const float4*)gB;
        float4 b1 = *(const float4*)(gB + 4);
        sts_bf16x8(sAb + stOff, a0, a1);
        sts_bf16x8(sBb + stOff, b0, b1);
    }
    __syncthreads();

    for (int t = 0; t < 16; t++) {
        const uint32_t tb = (uint32_t)(t & 1) * 4096u;
        float4 pa0, pa1, pb0, pb1;
        if (t < 15) {
            const float* nA = gA + (size_t)(t + 1) * 16 * D_DIM;
            const float* nB = gB + (size_t)(t + 1) * 16 * D_DIM;
            pa0 = *(const float4*)nA;  pa1 = *(const float4*)(nA + 4);
            pb0 = *(const float4*)nB;  pb1 = *(const float4*)(nB + 4);
        }
        uint32_t af[4][4], bf[2][4];
#pragma unroll
        for (int mi = 0; mi < 4; mi++) ldsm4t(af[mi], sAb + tb + aOff[mi]);
#pragma unroll
        for (int nb = 0; nb < 2; nb++) ldsm4t(bf[nb], sBb + tb + bOff[nb]);
#pragma unroll
        for (int mi = 0; mi < 4; mi++)
#pragma unroll
            for (int ni = 0; ni < 4; ni++)
                mma_bf16(c[mi][ni], af[mi],
                         bf[ni >> 1][(ni & 1) * 2], bf[ni >> 1][(ni & 1) * 2 + 1]);
        if (t < 15) {
            const uint32_t nbuf = (uint32_t)((t + 1) & 1) * 4096u;
            sts_bf16x8(sAb + nbuf + stOff, pa0, pa1);
            sts_bf16x8(sBb + nbuf + stOff, pb0, pb1);
        }
        __syncthreads();
    }

    // fused Hebbian epilogue (exact __f*_rn tree, unchanged numerics)
    const int rbase = blockIdx.y * 128 + mw * 64 + (lane >> 2);
    const int cbase = blockIdx.x * 128 + nw * 32 + 2 * (lane & 3);
#pragma unroll
    for (int mi = 0; mi < 4; mi++) {
#pragma unroll
        for (int half = 0; half < 2; half++) {
            const int r = rbase + mi * 16 + half * 8;
            const float mx  = stats[r];
            const float sum = stats[D_DIM + r];
            const float dec = decay[r];
#pragma unroll
            for (int ni = 0; ni < 4; ni++) {
                const int cc = cbase + ni * 8;
                const size_t idx = (size_t)r * D_DIM + cc;
                const float2 wp = *(const float2*)&Wmat[idx];
                const float v0 = c[mi][ni][half * 2 + 0];
                const float v1 = c[mi][ni][half * 2 + 1];
                float2 o;
                {
                    const float wsm = __fdiv_rn(expf(__fsub_rn(wp.x, mx)), sum);
                    const float Mv    = __fmul_rn(v0, 0.00390625f);
                    const float delta = __fmul_rn(wsm, Mv);
                    o.x = __fsub_rn(__fadd_rn(wp.x, delta), __fmul_rn(dec, wp.x));
                }
                {
                    const float wsm = __fdiv_rn(expf(__fsub_rn(wp.y, mx)), sum);
                    const float Mv    = __fmul_rn(v1, 0.00390625f);
                    const float delta = __fmul_rn(wsm, Mv);
                    o.y = __fsub_rn(__fadd_rn(wp.y, delta), __fmul_rn(dec, wp.y));
                }
                *(float2*)&out[idx] = o;
            }
        }
    }
}

// ============================================================================
// Combine kernels (unchanged)
// ============================================================================
__global__ void combine_store_kernel(const float* __restrict__ P,
                                     float* __restrict__ out, int n)
{
    const int i = (blockIdx.x * blockDim.x + threadIdx.x) * 4;
    const float4 p0 = *(const float4*)&P[i];
    const float4 p1 = *(const float4*)&P[n + i];
    float4 r;
    r.x = __fadd_rn(p0.x, p1.x);
    r.y = __fadd_rn(p0.y, p1.y);
    r.z = __fadd_rn(p0.z, p1.z);
    r.w = __fadd_rn(p0.w, p1.w);
    *(float4*)&out[i] = r;
}

__global__ void combine_acts_kernel(const float* __restrict__ P,
                                    const float* __restrict__ rec,
                                    const float* __restrict__ gab,
                                    const float* __restrict__ glu,
                                    float* __restrict__ out, int n)
{
    const int i = (blockIdx.x * blockDim.x + threadIdx.x) * 4;
    const float4 p0 = *(const float4*)&P[i];
    const float4 p1 = *(const float4*)&P[n + i];
    const float4 rc = *(const float4*)&rec[i];
    const float4 gb = *(const float4*)&gab[i];
    const float4 gl = *(const float4*)&glu[i];
    float tot[4] = {__fadd_rn(p0.x, p1.x), __fadd_rn(p0.y, p1.y),
                    __fadd_rn(p0.z, p1.z), __fadd_rn(p0.w, p1.w)};
    const float rcv[4] = {rc.x, rc.y, rc.z, rc.w};
    const float gbv[4] = {gb.x, gb.y, gb.z, gb.w};
    const float glv[4] = {gl.x, gl.y, gl.z, gl.w};
    float o[4];
#pragma unroll
    for (int q = 0; q < 4; q++) {
        float v = __fadd_rn(tot[q], rcv[q]);
        v = fmaxf(v, 0.f);
        const float t1  = __fsub_rn(1.0f, gbv[q]);
        const float t2  = __fadd_rn(t1, glv[q]);
        const float thr = __fmul_rn(0.5f, t2);
        o[q] = fmaxf(__fsub_rn(v, thr), 0.f);
    }
    *(float4*)&out[i] = make_float4(o[0], o[1], o[2], o[3]);
}

__global__ void combine_biasrelu_kernel(const float* __restrict__ P,
                                        const float* __restrict__ b1,
                                        float* __restrict__ out, int n)
{
    const int i = (blockIdx.x * blockDim.x + threadIdx.x) * 4;
    const float4 p0 = *(const float4*)&P[i];
    const float4 p1 = *(const float4*)&P[n + i];
    const float4 bb = *(const float4*)&b1[i & (D_DIM - 1)];
    float4 r;
    r.x = fmaxf(__fadd_rn(__fadd_rn(p0.x, p1.x), bb.x), 0.f);
    r.y = fmaxf(__fadd_rn(__fadd_rn(p0.y, p1.y), bb.y), 0.f);
    r.z = fmaxf(__fadd_rn(__fadd_rn(p0.z, p1.z), bb.z), 0.f);
    r.w = fmaxf(__fadd_rn(__fadd_rn(p0.w, p1.w), bb.w), 0.f);
    *(float4*)&out[i] = r;
}

__global__ void combine_neuro_kernel(const float* __restrict__ P,
                                     const float* __restrict__ b2,
                                     const float* __restrict__ dop,
                                     const float* __restrict__ ser,
                                     const float* __restrict__ glu,
                                     const float* __restrict__ gab,
                                     float* __restrict__ out)
{
    const int gid = blockIdx.x * blockDim.x + threadIdx.x;
    const int r = gid >> 12;
    const int d = gid & (D_DIM - 1);
    const size_t base = (size_t)r * D4 + d * 4;
    const float4 p0 = *(const float4*)&P[base];
    const float4 p1 = *(const float4*)&P[(size_t)B_DIM * D4 + base];
    const float4 bb = *(const float4*)&b2[d * 4];
    float t[4];
    t[0] = tanhf(__fadd_rn(__fadd_rn(p0.x, p1.x), bb.x));
    t[1] = tanhf(__fadd_rn(__fadd_rn(p0.y, p1.y), bb.y));
    t[2] = tanhf(__fadd_rn(__fadd_rn(p0.z, p1.z), bb.z));
    t[3] = tanhf(__fadd_rn(__fadd_rn(p0.w, p1.w), bb.w));
    const float inv = __fdiv_rn(1.0f, fmaxf(fabsf(t[1]), 1e-6f));
    const size_t src = (size_t)r * D_DIM + d;
    out[(size_t)(1 * B_DIM + r) * D_DIM + d] = __fadd_rn(dop[src], __fmul_rn(t[0], inv));
    out[(size_t)(2 * B_DIM + r) * D_DIM + d] = __fadd_rn(ser[src], t[1]);
    out[(size_t)(3 * B_DIM + r) * D_DIM + d] = __fadd_rn(glu[src], __fmul_rn(t[2], inv));
    out[(size_t)(4 * B_DIM + r) * D_DIM + d] = __fadd_rn(gab[src], __fmul_rn(t[3], inv));
}

// ------------- row softmax over [rows, 4096], one block per row -------------
__global__ void softmax_rows_kernel(const float* __restrict__ in,
                                    float* __restrict__ out)
{
    const int row = blockIdx.x;
    const int t   = threadIdx.x;
    const float* x = in + (size_t)row * D_DIM;
    float v[16];
    float mx = -3.402823e38f;
#pragma unroll
    for (int i = 0; i < 16; i++) { v[i] = x[t + i * 256]; mx = fmaxf(mx, v[i]); }

    __shared__ float red[256];
    red[t] = mx; __syncthreads();
    for (int s = 128; s > 0; s >>= 1) {
        if (t < s) red[t] = fmaxf(red[t], red[t + s]);
        __syncthreads();
    }
    const float m = red[0]; __syncthreads();

    float s = 0.f;
#pragma unroll
    for (int i = 0; i < 16; i++) { v[i] = expf(__fsub_rn(v[i], m)); s = __fadd_rn(s, v[i]); }
    red[t] = s; __syncthreads();
    for (int st = 128; st > 0; st >>= 1) {
        if (t < st) red[t] = __fadd_rn(red[t], red[t + st]);
        __syncthreads();
    }
    const float den = red[0];
#pragma unroll
    for (int i = 0; i < 16; i++)
        out[(size_t)row * D_DIM + t + i * 256] = __fdiv_rn(v[i], den);
}

// ------------- per-row max & sum(exp(x-max)) for a [4096,4096] matrix -------
__global__ void rowstats_kernel(const float* __restrict__ in,
                                float* __restrict__ stats)
{
    const int row = blockIdx.x;
    const int t   = threadIdx.x;
    const float* x = in + (size_t)row * D_DIM;
    float v[16];
    float mx = -3.402823e38f;
#pragma unroll
    for (int i = 0; i < 16; i++) { v[i] = x[t + i * 256]; mx = fmaxf(mx, v[i]); }

    __shared__ float red[256];
    red[t] = mx; __syncthreads();
    for (int s = 128; s > 0; s >>= 1) {
        if (t < s) red[t] = fmaxf(red[t], red[t + s]);
        __syncthreads();
    }
    const float m = red[0]; __syncthreads();

    float s = 0.f;
#pragma unroll
    for (int i = 0; i < 16; i++) s = __fadd_rn(s, expf(__fsub_rn(v[i], m)));
    red[t] = s; __syncthreads();
    for (int st = 128; st > 0; st >>= 1) {
        if (t < st) red[t] = __fadd_rn(red[t], red[t + st]);
        __syncthreads();
    }
    if (t == 0) { stats[row] = m; stats[D_DIM + row] = red[0]; }
}

// ------------- mod = (alpha[j] * dopamine) * serotonin ----------------------
__global__ void mod_kernel(const float* __restrict__ alpha,
                           const float* __restrict__ dop,
                           const float* __restrict__ ser,
                           float* __restrict__ out)
{
    const int i = blockIdx.x * blockDim.x + threadIdx.x;
    const int j = i & (D_DIM - 1);
    out[i] = __fmul_rn(__fmul_rn(alpha[j], dop[i]), ser[i]);
}

// ----------------------------------------------------------------------------
extern "C" void kernel_launch(void* const* d_in, const int* in_sizes, int n_in,
                              void* d_out, int out_size)
{
    const float* x      = (const float*)d_in[0];
    const float* W      = (const float*)d_in[1];
    const float* RW     = (const float*)d_in[2];
    const float* alpha  = (const float*)d_in[3];
    const float* decay  = (const float*)d_in[4];
    const float* dop    = (const float*)d_in[5];
    const float* ser    = (const float*)d_in[6];
    const float* glu    = (const float*)d_in[7];
    const float* gab    = (const float*)d_in[8];
    const float* prev   = (const float*)d_in[9];
    const float* W1     = (const float*)d_in[10];
    const float* b1     = (const float*)d_in[11];
    const float* W2     = (const float*)d_in[12];
    const float* b2     = (const float*)d_in[13];
    float* out = (float*)d_out;

    float *p_part, *p_rec, *p_asm_a, *p_asm_r, *p_mod, *p_hid, *p_stW, *p_stRW;
    cudaGetSymbolAddress((void**)&p_part,  g_part);
    cudaGetSymbolAddress((void**)&p_rec,   g_recurrent);
    cudaGetSymbolAddress((void**)&p_asm_a, g_asm_act);
    cudaGetSymbolAddress((void**)&p_asm_r, g_asm_rec);
    cudaGetSymbolAddress((void**)&p_mod,   g_mod);
    cudaGetSymbolAddress((void**)&p_hid,   g_hidden);
    cudaGetSymbolAddress((void**)&p_stW,   g_statsW);
    cudaGetSymbolAddress((void**)&p_stRW,  g_statsRW);

    float* acts_out  = out;
    float* Wnew_out  = out + (size_t)5 * B_DIM * D_DIM;
    float* RWnew_out = Wnew_out + (size_t)D_DIM * D_DIM;

    const dim3 blk(256);
    const dim3 grid_fwd(D_DIM / 128, B_DIM / 64, 2);
    const dim3 grid_w2(D4 / 128, B_DIM / 64, 2);
    const dim3 grid_hebb(D_DIM / 128, D_DIM / 128);   // 32 x 32
    const int  nBD = B_DIM * D_DIM;
    const int  cmb_blocks = nBD / (256 * 4);

    // independent prep first (also places fwd_gemm at ncu capture slot 5)
    mod_kernel<<<nBD / 256, blk>>>(alpha, dop, ser, p_mod);           // 0
    rowstats_kernel<<<D_DIM, blk>>>(W,  p_stW);                        // 1
    rowstats_kernel<<<D_DIM, blk>>>(RW, p_stRW);                       // 2

    // 1. recurrent = prev @ RW   (split-K=2 partials -> ordered combine)
    fwd_gemm_kernel<<<grid_fwd, blk>>>(prev, RW, p_part, B_DIM, D_DIM, D_DIM); // 3
    combine_store_kernel<<<cmb_blocks, blk>>>(p_part, p_rec, nBD);             // 4

    // 2. acts = relu(relu(x@W + rec) - thr)
    fwd_gemm_kernel<<<grid_fwd, blk>>>(x, W, p_part, B_DIM, D_DIM, D_DIM);     // 5
    combine_acts_kernel<<<cmb_blocks, blk>>>(p_part, p_rec, gab, glu, acts_out, nBD);

    // row softmax of acts and recurrent
    softmax_rows_kernel<<<B_DIM, blk>>>(acts_out, p_asm_a);
    softmax_rows_kernel<<<B_DIM, blk>>>(p_rec, p_asm_r);

    // Hebbian updates — bf16 tensor-core GEMMs with fused epilogue
    hebb_mma_kernel<<<grid_hebb, blk>>>(p_asm_a, p_mod, W,  p_stW,  decay, Wnew_out);
    hebb_mma_kernel<<<grid_hebb, blk>>>(p_asm_r, p_mod, RW, p_stRW, decay, RWnew_out);

    // hidden = relu(acts @ W1 + b1)
    fwd_gemm_kernel<<<grid_fwd, blk>>>(acts_out, W1, p_part, B_DIM, D_DIM, D_DIM);
    combine_biasrelu_kernel<<<cmb_blocks, blk>>>(p_part, b1, p_hid, nBD);

    // h = tanh(hidden @ W2 + b2) -> neuromodulator scatter
    fwd_gemm_kernel<<<grid_w2, blk>>>(p_hid, W2, p_part, B_DIM, D4, D_DIM);
    combine_neuro_kernel<<<nBD / 256, blk>>>(p_part, b2, dop, ser, glu, gab, out);
}